// round 1
// baseline (speedup 1.0000x reference)
#include <cuda_runtime.h>
#include <math.h>

#define E_    50000
#define N_    1000000
#define B_    8
#define L_    3
#define T_    3
#define NREL_ 401
#define R_    200
#define H_    256
#define G_    1024
#define TOPK_ 1000
#define BL_   24

// ---------------- device scratch (static; no allocations allowed) ----------------
__device__ int      g_cnt[2 * E_];
__device__ int      g_off_h[E_ + 1];
__device__ int      g_off_t[E_ + 1];
__device__ int      g_cur_h[E_];
__device__ int      g_cur_t[E_];
__device__ unsigned g_csr_h[N_];     // packed: tail | (rel<<16)
__device__ unsigned g_csr_t[N_];     // packed: head | (rel<<16)
__device__ float    g_s[2][BL_ * E_];
__device__ float    g_norm[2][BL_];
__device__ float    g_preq[6 * B_ * G_];
__device__ float    g_pree[6 * B_ * G_];
__device__ float    g_hst[6 * B_ * H_];
__device__ float    g_cst[6 * B_ * H_];
__device__ float    g_hseq[6 * 4 * B_ * H_];
__device__ float    g_gates[6 * B_ * G_];
__device__ float    g_logits[T_ * BL_ * NREL_];
__device__ float    g_w[T_ * BL_ * NREL_];
__device__ float    g_th[BL_];
__device__ int      g_fr_cnt;
__device__ unsigned g_fr_id[BL_ * E_];   // packed: (bl<<16) | e
__device__ float    g_fr_val[BL_ * E_];

__device__ __forceinline__ float sigm(float x) { return 1.f / (1.f + expf(-x)); }

// ---------------- CSR build ----------------
__global__ void zero_cnt_kernel() {
    int i = blockIdx.x * blockDim.x + threadIdx.x;
    if (i < 2 * E_) g_cnt[i] = 0;
}

__global__ void hist_kernel(const int* __restrict__ heads, const int* __restrict__ tails2) {
    int i = blockIdx.x * blockDim.x + threadIdx.x;
    if (i < N_) {
        atomicAdd(&g_cnt[heads[i]], 1);
        atomicAdd(&g_cnt[E_ + tails2[i]], 1);
    }
}

__global__ void scan_kernel() {
    __shared__ int tmp[1024];
    __shared__ int carry;
    for (int which = 0; which < 2; ++which) {
        const int* cnt = g_cnt + which * E_;
        int* off = which ? g_off_t : g_off_h;
        int* cur = which ? g_cur_t : g_cur_h;
        if (threadIdx.x == 0) carry = 0;
        __syncthreads();
        for (int base = 0; base < E_; base += 1024) {
            int i = base + threadIdx.x;
            int v = (i < E_) ? cnt[i] : 0;
            tmp[threadIdx.x] = v;
            __syncthreads();
            for (int d = 1; d < 1024; d <<= 1) {
                int t = (threadIdx.x >= d) ? tmp[threadIdx.x - d] : 0;
                __syncthreads();
                tmp[threadIdx.x] += t;
                __syncthreads();
            }
            int incl = tmp[threadIdx.x];
            int excl = incl - v;
            int c = carry;
            if (i < E_) { off[i] = c + excl; cur[i] = c + excl; }
            int tot = tmp[1023];
            __syncthreads();
            if (threadIdx.x == 0) carry = c + tot;
            __syncthreads();
        }
        if (threadIdx.x == 0) off[E_] = carry;
        __syncthreads();
    }
}

__global__ void scatter_kernel(const int* __restrict__ heads, const int* __restrict__ tails,
                               const int* __restrict__ rels, const int* __restrict__ tails2) {
    int i = blockIdx.x * blockDim.x + threadIdx.x;
    if (i < N_) {
        int h = heads[i], t = tails[i], r = rels[i], t2 = tails2[i];
        int p = atomicAdd(&g_cur_h[h], 1);
        g_csr_h[p] = (unsigned)t | ((unsigned)r << 16);
        int p2 = atomicAdd(&g_cur_t[t2], 1);
        g_csr_t[p2] = (unsigned)h | ((unsigned)r << 16);
    }
}

// ---------------- LSTM part ----------------
// ld = dir*3 + l  (dir 0 = forward, 1 = backward)
__global__ void pre_kernel(const float* __restrict__ emb, const int* __restrict__ input_r,
                           const float* __restrict__ Wihf, const float* __restrict__ Wihb,
                           const float* __restrict__ bihf, const float* __restrict__ bhhf,
                           const float* __restrict__ bihb, const float* __restrict__ bhhb) {
    int idx = blockIdx.x * blockDim.x + threadIdx.x;   // 6*8*1024
    int ld = idx >> 13;
    int b  = (idx >> 10) & 7;
    int j  = idx & 1023;
    int dir = ld / 3, l = ld % 3;
    const float* Wih = (dir == 0 ? Wihf : Wihb) + ((size_t)(l * G_ + j)) * H_;
    const float* bih = (dir == 0 ? bihf : bihb);
    const float* bhh = (dir == 0 ? bhhf : bhhb);
    float bias = bih[l * G_ + j] + bhh[l * G_ + j];
    const float4* w4 = (const float4*)Wih;
    const float4* q4 = (const float4*)(emb + (size_t)input_r[b] * H_);
    const float4* e4 = (const float4*)(emb + (size_t)(NREL_ - 1) * H_);
    float aq = 0.f, ae = 0.f;
#pragma unroll 16
    for (int k = 0; k < 64; ++k) {
        float4 w = w4[k], q = q4[k], e = e4[k];
        aq += w.x * q.x + w.y * q.y + w.z * q.z + w.w * q.w;
        ae += w.x * e.x + w.y * e.y + w.z * e.z + w.w * e.w;
    }
    g_preq[idx] = aq + bias;
    g_pree[idx] = ae + bias;
}

__global__ void gates_kernel(int s, const float* __restrict__ Whhf, const float* __restrict__ Whhb) {
    int idx = blockIdx.x * blockDim.x + threadIdx.x;
    int ld = idx >> 13;
    int b  = (idx >> 10) & 7;
    int j  = idx & 1023;
    int dir = ld / 3, l = ld % 3;
    const float* Whh = (dir == 0 ? Whhf : Whhb) + ((size_t)(l * G_ + j)) * H_;
    const float* h = g_hst + (ld * 8 + b) * H_;
    const float4* w4 = (const float4*)Whh;
    const float4* h4 = (const float4*)h;
    float acc = 0.f;
#pragma unroll 16
    for (int k = 0; k < 64; ++k) {
        float4 w = w4[k], x = h4[k];
        acc += w.x * x.x + w.y * x.y + w.z * x.z + w.w * x.w;
    }
    int use_e = (dir == 0) ? (s == 3) : (s == 0);
    float pre = (use_e ? g_pree : g_preq)[idx];
    g_gates[idx] = pre + acc;
}

__global__ void update_kernel(int s) {
    int idx = blockIdx.x * blockDim.x + threadIdx.x;   // 6*8*256
    if (idx >= 6 * B_ * H_) return;
    int ld = idx >> 11;
    int b  = (idx >> 8) & 7;
    int u  = idx & 255;
    int base = (ld * 8 + b) * G_;
    float gi, gf, gg, go, cprev;
    if (s == 0) {
        const float* src = (ld >= 3) ? g_pree : g_preq;   // bwd step0 sees emb[-1]
        gi = src[base + u]; gf = src[base + 256 + u];
        gg = src[base + 512 + u]; go = src[base + 768 + u];
        cprev = 0.f;
    } else {
        gi = g_gates[base + u]; gf = g_gates[base + 256 + u];
        gg = g_gates[base + 512 + u]; go = g_gates[base + 768 + u];
        cprev = g_cst[idx];
    }
    float c = sigm(gf) * cprev + sigm(gi) * tanhf(gg);
    float h = sigm(go) * tanhf(c);
    g_cst[idx] = c;
    g_hst[idx] = h;
    g_hseq[((ld * 4 + s) * 8 + b) * H_ + u] = h;
}

__global__ void logits_kernel(const float* __restrict__ linW, const float* __restrict__ linb) {
    int idx = blockIdx.x * blockDim.x + threadIdx.x;   // 8*3*3*401
    if (idx >= B_ * T_ * L_ * NREL_) return;
    int n = idx % NREL_;
    int r = idx / NREL_;
    int l = r % 3; r /= 3;
    int b = r % 8;
    int t = r / 8;
    const float4* hf = (const float4*)(g_hseq + ((l * 4 + t) * 8 + b) * H_);
    const float4* hb = (const float4*)(g_hseq + (((3 + l) * 4 + (3 - t)) * 8 + b) * H_);
    const float4* w1 = (const float4*)(linW + (size_t)n * 2 * H_);
    const float4* w2 = w1 + 64;
    float acc = linb[n];
#pragma unroll 16
    for (int k = 0; k < 64; ++k) {
        float4 a = hf[k], w = w1[k];
        acc += a.x * w.x + a.y * w.y + a.z * w.z + a.w * w.w;
        float4 c = hb[k], v = w2[k];
        acc += c.x * v.x + c.y * v.y + c.z * v.z + c.w * v.w;
    }
    g_logits[(t * BL_ + b * 3 + l) * NREL_ + n] = acc;
}

__global__ void softmax_kernel() {
    int row = blockIdx.x;   // 72 = T*BL
    const float* lg = g_logits + row * NREL_;
    float* wout = g_w + row * NREL_;
    __shared__ float buf[NREL_];
    __shared__ float red[128];
    int tid = threadIdx.x;
    float lmax = -1e30f;
    for (int i = tid; i < NREL_; i += 128) {
        float v = lg[i] * 0.1f;   // /TAU
        buf[i] = v;
        lmax = fmaxf(lmax, v);
    }
    red[tid] = lmax; __syncthreads();
    for (int o = 64; o > 0; o >>= 1) { if (tid < o) red[tid] = fmaxf(red[tid], red[tid + o]); __syncthreads(); }
    float m = red[0];
    __syncthreads();
    float lsum = 0.f;
    for (int i = tid; i < NREL_; i += 128) {
        float ex = expf(buf[i] - m);
        buf[i] = ex;
        lsum += ex;
    }
    red[tid] = lsum; __syncthreads();
    for (int o = 64; o > 0; o >>= 1) { if (tid < o) red[tid] += red[tid + o]; __syncthreads(); }
    float inv = 1.f / red[0];
    for (int i = tid; i < NREL_; i += 128) wout[i] = buf[i] * inv;
}

// ---------------- propagation ----------------
__global__ void zero_s_kernel(int w) {
    int i = blockIdx.x * blockDim.x + threadIdx.x;
    if (i < BL_ * E_) g_s[w][i] = 0.f;
    if (i < BL_) g_norm[w][i] = 0.f;
}

__global__ void frontier_init_kernel(const int* __restrict__ input_x) {
    int bl = threadIdx.x;
    if (bl < BL_) {
        int b = bl / 3;
        int e = input_x[b];
        g_fr_id[bl]  = ((unsigned)bl << 16) | (unsigned)e;
        g_fr_val[bl] = 1.f;
        g_norm[0][bl] = 1.f;
    }
    if (threadIdx.x == 0) g_fr_cnt = BL_;
}

// exact k-th largest via 4-pass radix select on float bits (values are >= 0)
__global__ void threshold_kernel(int pp) {
    int bl = blockIdx.x;
    const float* s = g_s[pp] + (size_t)bl * E_;
    __shared__ int hist[256];
    __shared__ unsigned sh_prefix, sh_mask;
    __shared__ int sh_krem;
    if (threadIdx.x == 0) { sh_prefix = 0u; sh_mask = 0u; sh_krem = TOPK_; }
    __syncthreads();
    for (int pass = 0; pass < 4; ++pass) {
        int shift = 24 - 8 * pass;
        for (int i = threadIdx.x; i < 256; i += blockDim.x) hist[i] = 0;
        __syncthreads();
        unsigned mask = sh_mask, pref = sh_prefix;
        for (int i = threadIdx.x; i < E_; i += blockDim.x) {
            unsigned b = __float_as_uint(s[i]);
            if ((b & mask) == pref) atomicAdd(&hist[(b >> shift) & 255u], 1);
        }
        __syncthreads();
        if (threadIdx.x == 0) {
            int cum = 0, krem = sh_krem, sel = 0, newk = krem;
            for (int bn = 255; bn >= 0; --bn) {
                int c = hist[bn];
                if (cum + c >= krem) { sel = bn; newk = krem - cum; break; }
                cum += c;
            }
            sh_prefix = pref | ((unsigned)sel << shift);
            sh_mask   = mask | (0xFFu << shift);
            sh_krem   = newk;
        }
        __syncthreads();
    }
    if (threadIdx.x == 0) {
        g_th[bl] = __uint_as_float(sh_prefix);
        if (bl == 0) g_fr_cnt = 0;
    }
}

__global__ void compact_kernel(int pp) {
    int idx = blockIdx.x * blockDim.x + threadIdx.x;
    if (idx >= BL_ * E_) return;
    float v = g_s[pp][idx];
    int bl = idx / E_;
    if (v > 0.f && v >= g_th[bl]) {
        int e = idx - bl * E_;
        int p = atomicAdd(&g_fr_cnt, 1);
        g_fr_id[p]  = ((unsigned)bl << 16) | (unsigned)e;
        g_fr_val[p] = v;
    }
}

__global__ void propagate_kernel(int t, int np, int nn, int sn) {
    int gtid = blockIdx.x * blockDim.x + threadIdx.x;
    int warp = gtid >> 5;
    int lane = threadIdx.x & 31;
    int nwarps = (gridDim.x * blockDim.x) >> 5;
    int cnt = g_fr_cnt;
    for (int ent = warp; ent < cnt; ent += nwarps) {
        unsigned id = g_fr_id[ent];
        int bl = id >> 16;
        int e  = id & 0xFFFFu;
        float nrm = g_norm[np][bl];
        float v = g_fr_val[ent] / fmaxf(nrm, 1e-7f);
        const float* wr = g_w + (t * BL_ + bl) * NREL_;
        float* outp = g_s[sn] + (size_t)bl * E_;
        float lsum = 0.f;
        if (lane == 0) {
            float m = wr[NREL_ - 1] * v;
            atomicAdd(&outp[e], m);
            lsum += m;
        }
        int a0 = g_off_h[e], a1 = g_off_h[e + 1];
        for (int i = a0 + lane; i < a1; i += 32) {
            unsigned pk = g_csr_h[i];
            float m = v * wr[pk >> 16];
            atomicAdd(&outp[pk & 0xFFFFu], m);
            lsum += m;
        }
        a0 = g_off_t[e]; a1 = g_off_t[e + 1];
        for (int i = a0 + lane; i < a1; i += 32) {
            unsigned pk = g_csr_t[i];
            float m = v * wr[(pk >> 16) + R_];
            atomicAdd(&outp[pk & 0xFFFFu], m);
            lsum += m;
        }
        for (int o = 16; o > 0; o >>= 1) lsum += __shfl_down_sync(0xffffffffu, lsum, o);
        if (lane == 0) atomicAdd(&g_norm[nn][bl], lsum);
    }
}

__global__ void out_kernel(float* __restrict__ out) {
    int idx = blockIdx.x * blockDim.x + threadIdx.x;
    if (idx >= B_ * E_) return;
    int b = idx / E_;
    int e = idx - b * E_;
    float acc = 0.f;
#pragma unroll
    for (int l = 0; l < L_; ++l) {
        int bl = b * 3 + l;
        acc += g_s[1][(size_t)bl * E_ + e] / fmaxf(g_norm[1][bl], 1e-7f);
    }
    out[idx] = acc;
}

// ---------------- launch ----------------
extern "C" void kernel_launch(void* const* d_in, const int* in_sizes, int n_in,
                              void* d_out, int out_size) {
    (void)in_sizes; (void)n_in; (void)out_size;
    const int*   input_x = (const int*)d_in[0];
    const int*   input_r = (const int*)d_in[1];
    const int*   e2      = (const int*)d_in[2];
    const int*   t2e     = (const int*)d_in[3];
    const int*   r2      = (const int*)d_in[4];
    const float* emb     = (const float*)d_in[5];
    const float* Wihf    = (const float*)d_in[6];
    const float* Whhf    = (const float*)d_in[7];
    const float* bihf    = (const float*)d_in[8];
    const float* bhhf    = (const float*)d_in[9];
    const float* Wihb    = (const float*)d_in[10];
    const float* Whhb    = (const float*)d_in[11];
    const float* bihb    = (const float*)d_in[12];
    const float* bhhb    = (const float*)d_in[13];
    const float* linW    = (const float*)d_in[14];
    const float* linb    = (const float*)d_in[15];
    float* out = (float*)d_out;

    const int* heads  = e2;            // e2triple[0]
    const int* tails2 = e2 + 2 * N_;   // e2triple[2]
    const int* tails  = t2e + N_;      // triple2e[1]
    const int* rels   = r2;            // r2triple[0]

    const int NB = (N_ + 255) / 256;          // 3907
    const int SB = (BL_ * E_ + 255) / 256;    // 4688

    // CSR build
    zero_cnt_kernel<<<(2 * E_ + 255) / 256, 256>>>();
    hist_kernel<<<NB, 256>>>(heads, tails2);
    scan_kernel<<<1, 1024>>>();
    scatter_kernel<<<NB, 256>>>(heads, tails, rels, tails2);

    // BiLSTM rule encoder
    pre_kernel<<<192, 256>>>(emb, input_r, Wihf, Wihb, bihf, bhhf, bihb, bhhb);
    update_kernel<<<48, 256>>>(0);
    for (int s = 1; s < 4; ++s) {
        gates_kernel<<<192, 256>>>(s, Whhf, Whhb);
        update_kernel<<<48, 256>>>(s);
    }
    logits_kernel<<<(B_ * T_ * L_ * NREL_ + 127) / 128, 128>>>(linW, linb);
    softmax_kernel<<<T_ * BL_, 128>>>();

    // hop 0: frontier = one-hot query entities
    zero_s_kernel<<<SB, 256>>>(1);
    frontier_init_kernel<<<1, 32>>>(input_x);
    propagate_kernel<<<1024, 256>>>(0, 0, 1, 1);
    // hop 1
    zero_s_kernel<<<SB, 256>>>(0);
    threshold_kernel<<<BL_, 256>>>(1);
    compact_kernel<<<SB, 256>>>(1);
    propagate_kernel<<<1024, 256>>>(1, 1, 0, 0);
    // hop 2
    zero_s_kernel<<<SB, 256>>>(1);
    threshold_kernel<<<BL_, 256>>>(0);
    compact_kernel<<<SB, 256>>>(0);
    propagate_kernel<<<1024, 256>>>(2, 0, 1, 1);

    out_kernel<<<(B_ * E_ + 255) / 256, 256>>>(out);
}

// round 2
// speedup vs baseline: 1.2456x; 1.2456x over previous
#include <cuda_runtime.h>
#include <math.h>

#define E_    50000
#define EPAD_ 50176
#define N_    1000000
#define B_    8
#define L_    3
#define T_    3
#define NREL_ 401
#define R_    200
#define H_    256
#define G_    1024
#define TOPK_ 1000
#define BL_   24

// ---------------- device scratch ----------------
__device__ int      g_cnt[2 * E_];
__device__ int      g_off_h[E_ + 1];
__device__ int      g_off_t[E_ + 1];
__device__ int      g_cur_h[E_];
__device__ int      g_cur_t[E_];
__device__ unsigned g_csr_h[N_];     // packed: tail | (rel<<16)
__device__ unsigned g_csr_t[N_];     // packed: head | (rel<<16)
__device__ float    g_s[2][BL_ * E_];
__device__ float    g_norm[2][BL_];
__device__ float    g_preq[6 * B_ * G_];
__device__ float    g_pree[6 * B_ * G_];
__device__ float    g_hst[6 * B_ * H_];
__device__ float    g_cst[6 * B_ * H_];
__device__ float    g_hseq[6 * 4 * B_ * H_];
__device__ float    g_gates[6 * B_ * G_];
__device__ float    g_logits[T_ * BL_ * NREL_];
__device__ float    g_w[T_ * BL_ * NREL_];
__device__ int      g_fr_cnt;
__device__ unsigned g_fr_id[BL_ * E_];   // packed: (bl<<16) | e
__device__ float    g_fr_val[BL_ * E_];

__device__ __forceinline__ float sigm(float x) { return 1.f / (1.f + expf(-x)); }

// ---------------- CSR build ----------------
__global__ void hist_kernel(const int4* __restrict__ h4, const int4* __restrict__ t24) {
    int i = blockIdx.x * blockDim.x + threadIdx.x;
    if (i < N_ / 4) {
        int4 h = h4[i], t = t24[i];
        atomicAdd(&g_cnt[h.x], 1); atomicAdd(&g_cnt[h.y], 1);
        atomicAdd(&g_cnt[h.z], 1); atomicAdd(&g_cnt[h.w], 1);
        atomicAdd(&g_cnt[E_ + t.x], 1); atomicAdd(&g_cnt[E_ + t.y], 1);
        atomicAdd(&g_cnt[E_ + t.z], 1); atomicAdd(&g_cnt[E_ + t.w], 1);
    }
}

// single block, thread-serial chunks + one 1024-wide scan per array
__global__ void scan_kernel() {
    __shared__ int tmp[1024];
    int tid = threadIdx.x;
    for (int which = 0; which < 2; ++which) {
        const int* cnt = g_cnt + which * E_;
        int* off = which ? g_off_t : g_off_h;
        int* cur = which ? g_cur_t : g_cur_h;
        int base = tid * 49;
        int sum = 0;
        for (int i = 0; i < 49; ++i) { int idx = base + i; if (idx < E_) sum += cnt[idx]; }
        tmp[tid] = sum;
        __syncthreads();
        for (int d = 1; d < 1024; d <<= 1) {
            int t = (tid >= d) ? tmp[tid - d] : 0;
            __syncthreads();
            tmp[tid] += t;
            __syncthreads();
        }
        int excl = tmp[tid] - sum;
        int total = tmp[1023];
        int run = excl;
        for (int i = 0; i < 49; ++i) {
            int idx = base + i;
            if (idx < E_) { off[idx] = run; cur[idx] = run; run += cnt[idx]; }
        }
        if (tid == 0) off[E_] = total;
        __syncthreads();
    }
}

__global__ void scatter_kernel(const int4* __restrict__ h4, const int4* __restrict__ t4,
                               const int4* __restrict__ r4, const int4* __restrict__ t24) {
    int i = blockIdx.x * blockDim.x + threadIdx.x;
    if (i < N_ / 4) {
        int4 h = h4[i], t = t4[i], r = r4[i], t2 = t24[i];
#define DO1(hx, tx, rx, t2x) { \
        int p = atomicAdd(&g_cur_h[hx], 1); \
        g_csr_h[p] = (unsigned)(tx) | ((unsigned)(rx) << 16); \
        int q = atomicAdd(&g_cur_t[t2x], 1); \
        g_csr_t[q] = (unsigned)(hx) | ((unsigned)(rx) << 16); }
        DO1(h.x, t.x, r.x, t2.x); DO1(h.y, t.y, r.y, t2.y);
        DO1(h.z, t.z, r.z, t2.z); DO1(h.w, t.w, r.w, t2.w);
#undef DO1
    }
}

// ---------------- LSTM (k-split, weights read once) ----------------
// 96 blocks x 256: thread = (row j of 6144, k-quarter p), all 8 batches
__global__ void pre_kernel(const float* __restrict__ emb, const int* __restrict__ input_r,
                           const float* __restrict__ Wihf, const float* __restrict__ Wihb,
                           const float* __restrict__ bihf, const float* __restrict__ bhhf,
                           const float* __restrict__ bihb, const float* __restrict__ bhhb) {
    int gt = blockIdx.x * 256 + threadIdx.x;
    int p = gt & 3;
    int row = gt >> 2;          // 0..6143
    int ld = row >> 10;
    int j = row & 1023;
    int dir = ld / 3, l = ld % 3;
    const float4* w4 = (const float4*)((dir ? Wihb : Wihf) + ((size_t)(l * G_ + j)) * H_) + p * 16;
    const float4* e4 = (const float4*)(emb + (size_t)(NREL_ - 1) * H_) + p * 16;
    const float4* q4[B_];
    float aq[B_];
#pragma unroll
    for (int b = 0; b < B_; ++b) {
        q4[b] = (const float4*)(emb + (size_t)input_r[b] * H_) + p * 16;
        aq[b] = 0.f;
    }
    float ae = 0.f;
#pragma unroll
    for (int k = 0; k < 16; ++k) {
        float4 w = w4[k];
        float4 e = e4[k];
        ae += w.x * e.x + w.y * e.y + w.z * e.z + w.w * e.w;
#pragma unroll
        for (int b = 0; b < B_; ++b) {
            float4 q = q4[b][k];
            aq[b] += w.x * q.x + w.y * q.y + w.z * q.z + w.w * q.w;
        }
    }
#pragma unroll
    for (int o = 1; o <= 2; o <<= 1) {
        ae += __shfl_xor_sync(0xffffffffu, ae, o);
#pragma unroll
        for (int b = 0; b < B_; ++b) aq[b] += __shfl_xor_sync(0xffffffffu, aq[b], o);
    }
    if (p == 0) {
        float bias = (dir ? bihb : bihf)[l * G_ + j] + (dir ? bhhb : bhhf)[l * G_ + j];
#pragma unroll
        for (int b = 0; b < B_; ++b) {
            int idx = (ld * 8 + b) * G_ + j;
            g_preq[idx] = aq[b] + bias;
            g_pree[idx] = ae + bias;
        }
    }
}

__global__ void gates_kernel(int s, const float* __restrict__ Whhf, const float* __restrict__ Whhb) {
    int gt = blockIdx.x * 256 + threadIdx.x;
    int p = gt & 3;
    int row = gt >> 2;
    int ld = row >> 10;
    int j = row & 1023;
    int dir = ld / 3, l = ld % 3;
    const float4* w4 = (const float4*)((dir ? Whhb : Whhf) + ((size_t)(l * G_ + j)) * H_) + p * 16;
    const float4* hbase = (const float4*)g_hst + (ld * 8) * 64 + p * 16;  // + b*64
    float acc[B_];
#pragma unroll
    for (int b = 0; b < B_; ++b) acc[b] = 0.f;
#pragma unroll
    for (int k = 0; k < 16; ++k) {
        float4 w = w4[k];
#pragma unroll
        for (int b = 0; b < B_; ++b) {
            float4 h = hbase[b * 64 + k];
            acc[b] += w.x * h.x + w.y * h.y + w.z * h.z + w.w * h.w;
        }
    }
#pragma unroll
    for (int o = 1; o <= 2; o <<= 1)
#pragma unroll
        for (int b = 0; b < B_; ++b) acc[b] += __shfl_xor_sync(0xffffffffu, acc[b], o);
    if (p == 0) {
        int use_e = (dir == 0) && (s == 3);
        const float* pre = use_e ? g_pree : g_preq;
#pragma unroll
        for (int b = 0; b < B_; ++b) {
            int idx = (ld * 8 + b) * G_ + j;
            g_gates[idx] = pre[idx] + acc[b];
        }
    }
}

__global__ void update_kernel(int s) {
    int idx = blockIdx.x * blockDim.x + threadIdx.x;   // 6*8*256 = 12288
    if (idx >= 6 * B_ * H_) return;
    int ld = idx >> 11;
    int b  = (idx >> 8) & 7;
    int u  = idx & 255;
    int base = (ld * 8 + b) * G_;
    float gi, gf, gg, go, cprev;
    if (s == 0) {
        const float* src = (ld >= 3) ? g_pree : g_preq;   // bwd step0 sees emb[-1]
        gi = src[base + u]; gf = src[base + 256 + u];
        gg = src[base + 512 + u]; go = src[base + 768 + u];
        cprev = 0.f;
    } else {
        gi = g_gates[base + u]; gf = g_gates[base + 256 + u];
        gg = g_gates[base + 512 + u]; go = g_gates[base + 768 + u];
        cprev = g_cst[idx];
    }
    float c = sigm(gf) * cprev + sigm(gi) * tanhf(gg);
    float h = sigm(go) * tanhf(c);
    g_cst[idx] = c;
    g_hst[idx] = h;
    g_hseq[((ld * 4 + s) * 8 + b) * H_ + u] = h;
}

// thread = (n, t, l, k-quarter p), all 8 batches; linW read 9x instead of 72x
__global__ void logits_kernel(const float* __restrict__ linW, const float* __restrict__ linb) {
    const int TOTAL = NREL_ * 9 * 4;   // 14436
    int gt = blockIdx.x * 256 + threadIdx.x;
    int g = (gt < TOTAL) ? gt : (TOTAL - 1);
    int n = g / 36;
    int rem = g % 36;
    int tl = rem >> 2;
    int p = g & 3;
    int t = tl / 3, l = tl % 3;
    const float4* w1 = (const float4*)(linW + (size_t)n * 2 * H_) + p * 16;
    const float4* w2 = w1 + 64;
    const float4* hf = (const float4*)g_hseq + ((l * 4 + t) * 8) * 64 + p * 16;
    const float4* hb = (const float4*)g_hseq + (((3 + l) * 4 + (3 - t)) * 8) * 64 + p * 16;
    float acc[B_];
#pragma unroll
    for (int b = 0; b < B_; ++b) acc[b] = 0.f;
#pragma unroll
    for (int k = 0; k < 16; ++k) {
        float4 wa = w1[k], wb = w2[k];
#pragma unroll
        for (int b = 0; b < B_; ++b) {
            float4 a = hf[b * 64 + k];
            float4 c = hb[b * 64 + k];
            acc[b] += a.x * wa.x + a.y * wa.y + a.z * wa.z + a.w * wa.w
                    + c.x * wb.x + c.y * wb.y + c.z * wb.z + c.w * wb.w;
        }
    }
#pragma unroll
    for (int o = 1; o <= 2; o <<= 1)
#pragma unroll
        for (int b = 0; b < B_; ++b) acc[b] += __shfl_xor_sync(0xffffffffu, acc[b], o);
    if (gt < TOTAL && p == 0) {
        float bb = linb[n];
#pragma unroll
        for (int b = 0; b < B_; ++b)
            g_logits[(t * BL_ + b * 3 + l) * NREL_ + n] = acc[b] + bb;
    }
}

__global__ void softmax_kernel() {
    int row = blockIdx.x;   // 72
    const float* lg = g_logits + row * NREL_;
    float* wout = g_w + row * NREL_;
    __shared__ float buf[NREL_];
    __shared__ float red[128];
    int tid = threadIdx.x;
    float lmax = -1e30f;
    for (int i = tid; i < NREL_; i += 128) {
        float v = lg[i] * 0.1f;
        buf[i] = v;
        lmax = fmaxf(lmax, v);
    }
    red[tid] = lmax; __syncthreads();
    for (int o = 64; o > 0; o >>= 1) { if (tid < o) red[tid] = fmaxf(red[tid], red[tid + o]); __syncthreads(); }
    float m = red[0];
    __syncthreads();
    float lsum = 0.f;
    for (int i = tid; i < NREL_; i += 128) {
        float ex = expf(buf[i] - m);
        buf[i] = ex;
        lsum += ex;
    }
    red[tid] = lsum; __syncthreads();
    for (int o = 64; o > 0; o >>= 1) { if (tid < o) red[tid] += red[tid + o]; __syncthreads(); }
    float inv = 1.f / red[0];
    for (int i = tid; i < NREL_; i += 128) wout[i] = buf[i] * inv;
}

// ---------------- hop 0: one block per (b,l), one-hot frontier ----------------
__global__ void hop0_kernel(const int* __restrict__ input_x) {
    int bl = blockIdx.x;
    int b = bl / 3;
    int e = input_x[b];
    const float* wr = g_w + bl * NREL_;   // t = 0
    float* outp = g_s[1] + (size_t)bl * E_;
    int tid = threadIdx.x;
    float lsum = 0.f;
    if (tid == 0) { float m = wr[NREL_ - 1]; atomicAdd(&outp[e], m); lsum = m; }
    int a0 = g_off_h[e], a1 = g_off_h[e + 1];
    for (int i = a0 + tid; i < a1; i += 256) {
        unsigned pk = g_csr_h[i];
        float m = wr[pk >> 16];
        atomicAdd(&outp[pk & 0xFFFFu], m);
        lsum += m;
    }
    a0 = g_off_t[e]; a1 = g_off_t[e + 1];
    for (int i = a0 + tid; i < a1; i += 256) {
        unsigned pk = g_csr_t[i];
        float m = wr[(pk >> 16) + R_];
        atomicAdd(&outp[pk & 0xFFFFu], m);
        lsum += m;
    }
    __shared__ float red[256];
    red[tid] = lsum; __syncthreads();
    for (int o = 128; o > 0; o >>= 1) { if (tid < o) red[tid] += red[tid + o]; __syncthreads(); }
    if (tid == 0) g_norm[1][bl] = red[0];
}

// ---------------- fused exact top-k threshold + compact ----------------
__global__ void tc_kernel(int pp) {
    int bl = blockIdx.x;
    const float* s = g_s[pp] + (size_t)bl * E_;
    __shared__ int hist[256];
    __shared__ unsigned shp, shm;
    __shared__ int shk;
    int tid = threadIdx.x, lane = tid & 31;
    if (tid == 0) { shp = 0u; shm = 0u; shk = TOPK_; }
    __syncthreads();
    for (int pass = 0; pass < 4; ++pass) {
        int shift = 24 - 8 * pass;
        if (tid < 256) hist[tid] = 0;
        __syncthreads();
        unsigned mask = shm, pref = shp;
        for (int i = tid; i < EPAD_; i += 1024) {
            unsigned bits = 0u; bool ok = false;
            if (i < E_) { bits = __float_as_uint(s[i]); ok = ((bits & mask) == pref); }
            int bin = (bits >> shift) & 255;
            unsigned act = __ballot_sync(0xffffffffu, ok);
            if (ok) {
                unsigned mm = __match_any_sync(act, bin);
                if (lane == __ffs(mm) - 1) atomicAdd(&hist[bin], __popc(mm));
            }
        }
        __syncthreads();
        if (tid == 0) {
            int cum = 0, krem = shk, sel = 0, newk = krem;
            for (int bn = 255; bn >= 0; --bn) {
                int c = hist[bn];
                if (cum + c >= krem) { sel = bn; newk = krem - cum; break; }
                cum += c;
            }
            shp = pref | ((unsigned)sel << shift);
            shm = mask | (0xFFu << shift);
            shk = newk;
        }
        __syncthreads();
    }
    float th = __uint_as_float(shp);
    for (int i = tid; i < EPAD_; i += 1024) {
        float v = 0.f; bool keep = false;
        if (i < E_) { v = s[i]; keep = (v > 0.f) && (v >= th); }
        unsigned m = __ballot_sync(0xffffffffu, keep);
        if (m) {
            int ldr = __ffs(m) - 1;
            int base;
            if (lane == ldr) base = atomicAdd(&g_fr_cnt, __popc(m));
            base = __shfl_sync(0xffffffffu, base, ldr);
            if (keep) {
                int off = base + __popc(m & ((1u << lane) - 1u));
                g_fr_id[off]  = ((unsigned)bl << 16) | (unsigned)i;
                g_fr_val[off] = v;
            }
        }
    }
}

// ---------------- sparse propagate (warp per frontier entry) ----------------
__global__ void propagate_kernel(int t, int np, int nn, int sn) {
    int gtid = blockIdx.x * blockDim.x + threadIdx.x;
    int warp = gtid >> 5;
    int lane = threadIdx.x & 31;
    int nwarps = (gridDim.x * blockDim.x) >> 5;
    int cnt = g_fr_cnt;
    for (int ent = warp; ent < cnt; ent += nwarps) {
        unsigned id = g_fr_id[ent];
        int bl = id >> 16;
        int e  = id & 0xFFFFu;
        float nrm = g_norm[np][bl];
        float v = g_fr_val[ent] / fmaxf(nrm, 1e-7f);
        const float* wr = g_w + (t * BL_ + bl) * NREL_;
        float* outp = g_s[sn] + (size_t)bl * E_;
        float lsum = 0.f;
        if (lane == 0) {
            float m = wr[NREL_ - 1] * v;
            atomicAdd(&outp[e], m);
            lsum += m;
        }
        int a0 = g_off_h[e], a1 = g_off_h[e + 1];
        for (int i = a0 + lane; i < a1; i += 32) {
            unsigned pk = g_csr_h[i];
            float m = v * wr[pk >> 16];
            atomicAdd(&outp[pk & 0xFFFFu], m);
            lsum += m;
        }
        a0 = g_off_t[e]; a1 = g_off_t[e + 1];
        for (int i = a0 + lane; i < a1; i += 32) {
            unsigned pk = g_csr_t[i];
            float m = v * wr[(pk >> 16) + R_];
            atomicAdd(&outp[pk & 0xFFFFu], m);
            lsum += m;
        }
        for (int o = 16; o > 0; o >>= 1) lsum += __shfl_down_sync(0xffffffffu, lsum, o);
        if (lane == 0) atomicAdd(&g_norm[nn][bl], lsum);
    }
}

__global__ void out_kernel(float* __restrict__ out) {
    int idx = blockIdx.x * blockDim.x + threadIdx.x;
    if (idx >= B_ * E_) return;
    int b = idx / E_;
    int e = idx - b * E_;
    float acc = 0.f;
#pragma unroll
    for (int l = 0; l < L_; ++l) {
        int bl = b * 3 + l;
        acc += g_s[1][(size_t)bl * E_ + e] / fmaxf(g_norm[1][bl], 1e-7f);
    }
    out[idx] = acc;
}

// ---------------- launch ----------------
extern "C" void kernel_launch(void* const* d_in, const int* in_sizes, int n_in,
                              void* d_out, int out_size) {
    (void)in_sizes; (void)n_in; (void)out_size;
    const int*   input_x = (const int*)d_in[0];
    const int*   input_r = (const int*)d_in[1];
    const int*   e2      = (const int*)d_in[2];
    const int*   t2e     = (const int*)d_in[3];
    const int*   r2      = (const int*)d_in[4];
    const float* emb     = (const float*)d_in[5];
    const float* Wihf    = (const float*)d_in[6];
    const float* Whhf    = (const float*)d_in[7];
    const float* bihf    = (const float*)d_in[8];
    const float* bhhf    = (const float*)d_in[9];
    const float* Wihb    = (const float*)d_in[10];
    const float* Whhb    = (const float*)d_in[11];
    const float* bihb    = (const float*)d_in[12];
    const float* bhhb    = (const float*)d_in[13];
    const float* linW    = (const float*)d_in[14];
    const float* linb    = (const float*)d_in[15];
    float* out = (float*)d_out;

    const int4* heads4  = (const int4*)e2;
    const int4* tails24 = (const int4*)(e2 + 2 * N_);
    const int4* tails4  = (const int4*)(t2e + N_);
    const int4* rels4   = (const int4*)r2;

    static cudaStream_t s2 = nullptr;
    static cudaEvent_t evF = nullptr, evJ = nullptr;
    if (s2 == nullptr) {
        cudaStreamCreateWithFlags(&s2, cudaStreamNonBlocking);
        cudaEventCreateWithFlags(&evF, cudaEventDisableTiming);
        cudaEventCreateWithFlags(&evJ, cudaEventDisableTiming);
    }

    void *p_cnt, *p_s, *p_norm, *p_frc;
    cudaGetSymbolAddress(&p_cnt, g_cnt);
    cudaGetSymbolAddress(&p_s, g_s);
    cudaGetSymbolAddress(&p_norm, g_norm);
    cudaGetSymbolAddress(&p_frc, g_fr_cnt);
    float* s0p = (float*)p_s;
    float* s1p = s0p + BL_ * E_;
    float* n1p = (float*)p_norm + BL_;

    const int NB4 = (N_ / 4 + 255) / 256;

    // fork: side stream runs LSTM/logits/softmax + state memsets concurrently with CSR build
    cudaEventRecord(evF, 0);
    cudaStreamWaitEvent(s2, evF, 0);

    // main stream: CSR build
    cudaMemsetAsync(p_cnt, 0, sizeof(int) * 2 * E_, 0);
    hist_kernel<<<NB4, 256>>>(heads4, tails24);
    scan_kernel<<<1, 1024>>>();
    scatter_kernel<<<NB4, 256>>>(heads4, tails4, rels4, tails24);

    // side stream
    cudaMemsetAsync(s0p, 0, sizeof(float) * BL_ * E_, s2);
    cudaMemsetAsync(s1p, 0, sizeof(float) * BL_ * E_, s2);
    cudaMemsetAsync(p_norm, 0, sizeof(float) * 2 * BL_, s2);
    cudaMemsetAsync(p_frc, 0, sizeof(int), s2);
    pre_kernel<<<96, 256, 0, s2>>>(emb, input_r, Wihf, Wihb, bihf, bhhf, bihb, bhhb);
    update_kernel<<<12, 1024, 0, s2>>>(0);
    for (int s = 1; s < 4; ++s) {
        gates_kernel<<<96, 256, 0, s2>>>(s, Whhf, Whhb);
        update_kernel<<<12, 1024, 0, s2>>>(s);
    }
    logits_kernel<<<(NREL_ * 9 * 4 + 255) / 256, 256, 0, s2>>>(linW, linb);
    softmax_kernel<<<T_ * BL_, 128, 0, s2>>>();
    cudaEventRecord(evJ, s2);
    cudaStreamWaitEvent(0, evJ, 0);

    // hop 0 (one-hot frontier)
    hop0_kernel<<<BL_, 256>>>(input_x);
    // hop 1
    tc_kernel<<<BL_, 1024>>>(1);
    propagate_kernel<<<512, 256>>>(1, 1, 0, 0);
    // hop 2
    cudaMemsetAsync(s1p, 0, sizeof(float) * BL_ * E_, 0);
    cudaMemsetAsync(n1p, 0, sizeof(float) * BL_, 0);
    cudaMemsetAsync(p_frc, 0, sizeof(int), 0);
    tc_kernel<<<BL_, 1024>>>(0);
    propagate_kernel<<<512, 256>>>(2, 0, 1, 1);

    out_kernel<<<(B_ * E_ + 255) / 256, 256>>>(out);
}